// round 9
// baseline (speedup 1.0000x reference)
#include <cuda_runtime.h>
#include <cstdint>
#include <cstddef>

// Problem constants
#define T_TOKENS 65536
#define DM 2048
#define NE 64

// Structure: 64-thread CTAs (2 warps), ONE token per thread, all 64 experts
// accumulated per thread as 32 packed f32x2 pairs. W staged per-chunk in smem
// (k-major, double buffered); x streamed per-thread from global (1 line/chunk).
#define KC 32
#define NCHUNK (DM / KC)     // 64
#define THREADS 64
#define TCTA 64              // tokens per CTA
#define WSS 68               // ws row stride in floats (16B-aligned rows)

// Output layout (flattened tuple, all float32) — validated R4+:
#define TP_OFF ((size_t)T_TOKENS * NE)
#define LG_OFF ((size_t)T_TOKENS * NE + T_TOKENS)

typedef unsigned long long ull;

__device__ __forceinline__ ull fma2(ull a, ull b, ull c) {
    ull d;
    asm("fma.rn.f32x2 %0, %1, %2, %3;" : "=l"(d) : "l"(a), "l"(b), "l"(c));
    return d;
}
__device__ __forceinline__ ull dup2(float w) {
    ull d;
    asm("mov.b64 %0, {%1, %1};" : "=l"(d) : "f"(w));
    return d;
}
__device__ __forceinline__ float2 unpack2(ull u) {
    float2 f;
    asm("mov.b64 {%0, %1}, %2;" : "=f"(f.x), "=f"(f.y) : "l"(u));
    return f;
}

__global__ void __launch_bounds__(THREADS, 6)
router_kernel(const float* __restrict__ x,
              const float* __restrict__ W,
              float* __restrict__ out) {
    // ws[buf][k][e] = W[e][k0+k]; rows 68 floats (272B, 16B-aligned).
    // Compute load: ulonglong2 at &ws[buf][k][4*jj] — uniform address across
    // the warp -> LDS.128 broadcast (conflict-degree 1).
    __shared__ __align__(16) float ws[2][KC][WSS];   // 17408 B

    const int tid = threadIdx.x;
    const int t   = blockIdx.x * TCTA + tid;         // this thread's token
    const float* xrow = x + (size_t)t * DM;

    // W fill mapping: lanes 0..7 cover 128B of one expert row (coalesced LDG),
    // 4 rows per warp per pass, 8 passes cover e = 0..63.
    const int fe = tid >> 3;          // base expert row 0..7
    const int fk = (tid & 7) * 4;     // float offset within chunk

    // acc[m] = packed logits for experts (2m, 2m+1) of token t
    ull acc[32];
#pragma unroll
    for (int m = 0; m < 32; m++) acc[m] = 0ull;

    float4 wpre[8];

    // ---- prologue: chunk 0 ----
#pragma unroll
    for (int rr = 0; rr < 8; rr++)
        wpre[rr] = *(const float4*)(W + (size_t)(fe + 8 * rr) * DM + fk);
    float4 xcur = *(const float4*)(xrow);   // warms token line for chunk 0

#pragma unroll
    for (int rr = 0; rr < 8; rr++) {
        const int e = fe + 8 * rr;
        ws[0][fk + 0][e] = wpre[rr].x;
        ws[0][fk + 1][e] = wpre[rr].y;
        ws[0][fk + 2][e] = wpre[rr].z;
        ws[0][fk + 3][e] = wpre[rr].w;
    }
    __syncthreads();

    for (int c = 0; c < NCHUNK; c++) {
        const int cur = c & 1;
        const int k0  = c * KC;
        const bool last = (c + 1 == NCHUNK);
        const int k0n = last ? 0 : k0 + KC;

        // ---- prefetch chunk c+1 (W -> regs, x line-warm) ----
#pragma unroll
        for (int rr = 0; rr < 8; rr++)
            wpre[rr] = *(const float4*)(W + (size_t)(fe + 8 * rr) * DM + k0n + fk);
        float4 xnext = *(const float4*)(xrow + k0n);

        // ---- compute chunk c ----
        // g = 0 uses the prefetched xcur; g = 1..7 are L1 hits on the same line.
        {
#pragma unroll
            for (int q = 0; q < 4; q++) {
                const float xq = (q == 0) ? xcur.x : (q == 1) ? xcur.y
                               : (q == 2) ? xcur.z : xcur.w;
                const ull a = dup2(xq);
#pragma unroll
                for (int jj = 0; jj < 16; jj++) {
                    ulonglong2 w2 = *(const ulonglong2*)&ws[cur][q][4 * jj];
                    acc[2 * jj]     = fma2(a, w2.x, acc[2 * jj]);
                    acc[2 * jj + 1] = fma2(a, w2.y, acc[2 * jj + 1]);
                }
            }
        }
#pragma unroll 2
        for (int g = 1; g < 8; g++) {
            float4 xv = *(const float4*)(xrow + k0 + g * 4);
#pragma unroll
            for (int q = 0; q < 4; q++) {
                const int kk = g * 4 + q;
                const float xq = (q == 0) ? xv.x : (q == 1) ? xv.y
                               : (q == 2) ? xv.z : xv.w;
                const ull a = dup2(xq);
#pragma unroll
                for (int jj = 0; jj < 16; jj++) {
                    ulonglong2 w2 = *(const ulonglong2*)&ws[cur][kk][4 * jj];
                    acc[2 * jj]     = fma2(a, w2.x, acc[2 * jj]);
                    acc[2 * jj + 1] = fma2(a, w2.y, acc[2 * jj + 1]);
                }
            }
        }

        // ---- stage chunk c+1 into the other buffer ----
        if (!last) {
            const int nxt = cur ^ 1;
#pragma unroll
            for (int rr = 0; rr < 8; rr++) {
                const int e = fe + 8 * rr;
                ws[nxt][fk + 0][e] = wpre[rr].x;
                ws[nxt][fk + 1][e] = wpre[rr].y;
                ws[nxt][fk + 2][e] = wpre[rr].z;
                ws[nxt][fk + 3][e] = wpre[rr].w;
            }
            __syncthreads();
        }
        xcur = xnext;
    }

    // ---- epilogue: this thread owns ALL 64 logits of token t ----
    float lg[NE];
#pragma unroll
    for (int m = 0; m < 32; m++) {
        float2 f = unpack2(acc[m]);
        lg[2 * m]     = f.x;
        lg[2 * m + 1] = f.y;
    }

    // argmax (ascending e, strict '>' keeps first max -> matches jnp.argmax)
    float mx = lg[0];
    int   ex = 0;
#pragma unroll
    for (int e = 1; e < NE; e++)
        if (lg[e] > mx) { mx = lg[e]; ex = e; }

    float s = 0.f;
#pragma unroll
    for (int e = 0; e < NE; e++) s += __expf(lg[e] - mx);

    // stores: per-thread full rows (one-hot + logits), float4
    float* ohp = out + (size_t)t * NE;
    float* lgp = out + LG_OFF + (size_t)t * NE;
#pragma unroll
    for (int e4 = 0; e4 < NE; e4 += 4) {
        float4 lv = make_float4(lg[e4], lg[e4 + 1], lg[e4 + 2], lg[e4 + 3]);
        float4 ov = make_float4(e4 == ex ? 1.f : 0.f,
                                e4 + 1 == ex ? 1.f : 0.f,
                                e4 + 2 == ex ? 1.f : 0.f,
                                e4 + 3 == ex ? 1.f : 0.f);
        *(float4*)(lgp + e4) = lv;
        *(float4*)(ohp + e4) = ov;
    }
    out[TP_OFF + t] = 1.0f / s;
}

extern "C" void kernel_launch(void* const* d_in, const int* in_sizes, int n_in,
                              void* d_out, int out_size) {
    const float* x = (const float*)d_in[0];   // [65536, 2048] f32
    const float* W = (const float*)d_in[1];   // [64, 2048] f32
    float* out = (float*)d_out;

    dim3 grid(T_TOKENS / TCTA);   // 1024 CTAs x 64 threads
    dim3 block(THREADS);
    router_kernel<<<grid, block>>>(x, W, out);
}

// round 10
// speedup vs baseline: 1.0014x; 1.0014x over previous
#include <cuda_runtime.h>
#include <cstdint>
#include <cstddef>

// Problem constants
#define T_TOKENS 65536
#define DM 2048
#define NE 64

// Structure: 64-thread CTAs (2 warps), ONE token per thread, all 64 experts
// accumulated per thread as 32 packed f32x2 pairs. W staged per-chunk in smem
// (k-major, double buffered); x streamed per-thread from global (1 line/chunk).
#define KC 32
#define NCHUNK (DM / KC)     // 64
#define THREADS 64
#define TCTA 64              // tokens per CTA
#define WSS 68               // ws row stride in floats (16B-aligned rows)

// Output layout (flattened tuple, all float32) — validated R4+:
#define TP_OFF ((size_t)T_TOKENS * NE)
#define LG_OFF ((size_t)T_TOKENS * NE + T_TOKENS)

typedef unsigned long long ull;

__device__ __forceinline__ ull fma2(ull a, ull b, ull c) {
    ull d;
    asm("fma.rn.f32x2 %0, %1, %2, %3;" : "=l"(d) : "l"(a), "l"(b), "l"(c));
    return d;
}
__device__ __forceinline__ ull dup2(float w) {
    ull d;
    asm("mov.b64 %0, {%1, %1};" : "=l"(d) : "f"(w));
    return d;
}
__device__ __forceinline__ float2 unpack2(ull u) {
    float2 f;
    asm("mov.b64 {%0, %1}, %2;" : "=f"(f.x), "=f"(f.y) : "l"(u));
    return f;
}

__global__ void __launch_bounds__(THREADS, 6)
router_kernel(const float* __restrict__ x,
              const float* __restrict__ W,
              float* __restrict__ out) {
    // ws[buf][k][e] = W[e][k0+k]; rows 68 floats (272B, 16B-aligned).
    // Compute load: ulonglong2 at &ws[buf][k][4*jj] — uniform address across
    // the warp -> LDS.128 broadcast (conflict-degree 1).
    __shared__ __align__(16) float ws[2][KC][WSS];   // 17408 B

    const int tid = threadIdx.x;
    const int t   = blockIdx.x * TCTA + tid;         // this thread's token
    const float* xrow = x + (size_t)t * DM;

    // W fill mapping: lanes 0..7 cover 128B of one expert row (coalesced LDG),
    // 4 rows per warp per pass, 8 passes cover e = 0..63.
    const int fe = tid >> 3;          // base expert row 0..7
    const int fk = (tid & 7) * 4;     // float offset within chunk

    // acc[m] = packed logits for experts (2m, 2m+1) of token t
    ull acc[32];
#pragma unroll
    for (int m = 0; m < 32; m++) acc[m] = 0ull;

    float4 wpre[8];

    // ---- prologue: chunk 0 ----
#pragma unroll
    for (int rr = 0; rr < 8; rr++)
        wpre[rr] = *(const float4*)(W + (size_t)(fe + 8 * rr) * DM + fk);
    float4 xcur = *(const float4*)(xrow);   // warms token line for chunk 0

#pragma unroll
    for (int rr = 0; rr < 8; rr++) {
        const int e = fe + 8 * rr;
        ws[0][fk + 0][e] = wpre[rr].x;
        ws[0][fk + 1][e] = wpre[rr].y;
        ws[0][fk + 2][e] = wpre[rr].z;
        ws[0][fk + 3][e] = wpre[rr].w;
    }
    __syncthreads();

    for (int c = 0; c < NCHUNK; c++) {
        const int cur = c & 1;
        const int k0  = c * KC;
        const bool last = (c + 1 == NCHUNK);
        const int k0n = last ? 0 : k0 + KC;

        // ---- prefetch chunk c+1 (W -> regs, x line-warm) ----
#pragma unroll
        for (int rr = 0; rr < 8; rr++)
            wpre[rr] = *(const float4*)(W + (size_t)(fe + 8 * rr) * DM + k0n + fk);
        float4 xnext = *(const float4*)(xrow + k0n);

        // ---- compute chunk c ----
        // g = 0 uses the prefetched xcur; g = 1..7 are L1 hits on the same line.
        {
#pragma unroll
            for (int q = 0; q < 4; q++) {
                const float xq = (q == 0) ? xcur.x : (q == 1) ? xcur.y
                               : (q == 2) ? xcur.z : xcur.w;
                const ull a = dup2(xq);
#pragma unroll
                for (int jj = 0; jj < 16; jj++) {
                    ulonglong2 w2 = *(const ulonglong2*)&ws[cur][q][4 * jj];
                    acc[2 * jj]     = fma2(a, w2.x, acc[2 * jj]);
                    acc[2 * jj + 1] = fma2(a, w2.y, acc[2 * jj + 1]);
                }
            }
        }
#pragma unroll 2
        for (int g = 1; g < 8; g++) {
            float4 xv = *(const float4*)(xrow + k0 + g * 4);
#pragma unroll
            for (int q = 0; q < 4; q++) {
                const int kk = g * 4 + q;
                const float xq = (q == 0) ? xv.x : (q == 1) ? xv.y
                               : (q == 2) ? xv.z : xv.w;
                const ull a = dup2(xq);
#pragma unroll
                for (int jj = 0; jj < 16; jj++) {
                    ulonglong2 w2 = *(const ulonglong2*)&ws[cur][kk][4 * jj];
                    acc[2 * jj]     = fma2(a, w2.x, acc[2 * jj]);
                    acc[2 * jj + 1] = fma2(a, w2.y, acc[2 * jj + 1]);
                }
            }
        }

        // ---- stage chunk c+1 into the other buffer ----
        if (!last) {
            const int nxt = cur ^ 1;
#pragma unroll
            for (int rr = 0; rr < 8; rr++) {
                const int e = fe + 8 * rr;
                ws[nxt][fk + 0][e] = wpre[rr].x;
                ws[nxt][fk + 1][e] = wpre[rr].y;
                ws[nxt][fk + 2][e] = wpre[rr].z;
                ws[nxt][fk + 3][e] = wpre[rr].w;
            }
            __syncthreads();
        }
        xcur = xnext;
    }

    // ---- epilogue: this thread owns ALL 64 logits of token t ----
    float lg[NE];
#pragma unroll
    for (int m = 0; m < 32; m++) {
        float2 f = unpack2(acc[m]);
        lg[2 * m]     = f.x;
        lg[2 * m + 1] = f.y;
    }

    // argmax (ascending e, strict '>' keeps first max -> matches jnp.argmax)
    float mx = lg[0];
    int   ex = 0;
#pragma unroll
    for (int e = 1; e < NE; e++)
        if (lg[e] > mx) { mx = lg[e]; ex = e; }

    float s = 0.f;
#pragma unroll
    for (int e = 0; e < NE; e++) s += __expf(lg[e] - mx);

    // stores: per-thread full rows (one-hot + logits), float4
    float* ohp = out + (size_t)t * NE;
    float* lgp = out + LG_OFF + (size_t)t * NE;
#pragma unroll
    for (int e4 = 0; e4 < NE; e4 += 4) {
        float4 lv = make_float4(lg[e4], lg[e4 + 1], lg[e4 + 2], lg[e4 + 3]);
        float4 ov = make_float4(e4 == ex ? 1.f : 0.f,
                                e4 + 1 == ex ? 1.f : 0.f,
                                e4 + 2 == ex ? 1.f : 0.f,
                                e4 + 3 == ex ? 1.f : 0.f);
        *(float4*)(lgp + e4) = lv;
        *(float4*)(ohp + e4) = ov;
    }
    out[TP_OFF + t] = 1.0f / s;
}

extern "C" void kernel_launch(void* const* d_in, const int* in_sizes, int n_in,
                              void* d_out, int out_size) {
    const float* x = (const float*)d_in[0];   // [65536, 2048] f32
    const float* W = (const float*)d_in[1];   // [64, 2048] f32
    float* out = (float*)d_out;

    dim3 grid(T_TOKENS / TCTA);   // 1024 CTAs x 64 threads
    dim3 block(THREADS);
    router_kernel<<<grid, block>>>(x, W, out);
}